// round 3
// baseline (speedup 1.0000x reference)
#include <cuda_runtime.h>
#include <cuda_fp16.h>
#include <math.h>

// Problem constants (fixed by the dataset)
#define NN      128000      // nodes = B*NG
#define EE      4096000     // edges = B*EG
#define BB      64          // graphs
#define NG      2000        // nodes per graph
#define KTOP    1600
#define EMB     64
#define G1      32
#define G2      32
#define DENSE   64
#define NCLS    10

// ---------------- device scratch ----------------
__device__ int            g_deg[NN];
__device__ int            g_partial[NN];
__device__ int            g_bsum[256];
__device__ int            g_bbase[256];
__device__ int            g_off[NN + 1];
__device__ unsigned char  g_rank[EE];
__device__ unsigned short g_csr16[EE];
__device__ float          g_dinv[NN];
__device__ __align__(16) __half g_bufA[NN * 32];  // proj1 out / final h2 (fp16)
__device__ __align__(16) __half g_bufB[NN * 32];  // dinv*(h1@W2) (fp16)
__device__ float          g_score[NN];

// ---------------- half8 helpers ----------------
__device__ __forceinline__ void add8(float* a, uint4 r) {
    float2 f;
    f = __half22float2(*(__half2*)&r.x); a[0] += f.x; a[1] += f.y;
    f = __half22float2(*(__half2*)&r.y); a[2] += f.x; a[3] += f.y;
    f = __half22float2(*(__half2*)&r.z); a[4] += f.x; a[5] += f.y;
    f = __half22float2(*(__half2*)&r.w); a[6] += f.x; a[7] += f.y;
}
__device__ __forceinline__ uint4 pack8(const float* h) {
    uint4 r;
    __half2 p;
    p = __floats2half2_rn(h[0], h[1]); r.x = *(unsigned*)&p;
    p = __floats2half2_rn(h[2], h[3]); r.y = *(unsigned*)&p;
    p = __floats2half2_rn(h[4], h[5]); r.z = *(unsigned*)&p;
    p = __floats2half2_rn(h[6], h[7]); r.w = *(unsigned*)&p;
    return r;
}

// ---------------- CSR build ----------------
__global__ void k_zero_deg() {
    int i = blockIdx.x * blockDim.x + threadIdx.x;
    if (i < NN / 4) ((int4*)g_deg)[i] = make_int4(0, 0, 0, 0);
}

__global__ void k_count_deg(const int* __restrict__ ei) {
    int i = blockIdx.x * blockDim.x + threadIdx.x;
    if (i >= EE / 4) return;
    int4 d4 = ((const int4*)(ei + EE))[i];
    uchar4 r;
    r.x = (unsigned char)atomicAdd(&g_deg[d4.x], 1);
    r.y = (unsigned char)atomicAdd(&g_deg[d4.y], 1);
    r.z = (unsigned char)atomicAdd(&g_deg[d4.z], 1);
    r.w = (unsigned char)atomicAdd(&g_deg[d4.w], 1);
    ((uchar4*)g_rank)[i] = r;
}

__global__ void k_scan1() {
    __shared__ int s[1024];
    int tid = threadIdx.x;
    int gid = blockIdx.x * 1024 + tid;
    int v = (gid < NN) ? g_deg[gid] : 0;
    int sum = v;
    s[tid] = sum;
    __syncthreads();
    for (int off = 1; off < 1024; off <<= 1) {
        int t = (tid >= off) ? s[tid - off] : 0;
        __syncthreads();
        sum += t;
        s[tid] = sum;
        __syncthreads();
    }
    if (gid < NN) g_partial[gid] = sum - v;
    if (tid == 1023) g_bsum[blockIdx.x] = sum;
}

__global__ void k_scan2(int nblocks) {
    __shared__ int s[128];
    int tid = threadIdx.x;
    int v = (tid < nblocks) ? g_bsum[tid] : 0;
    int sum = v;
    s[tid] = sum;
    __syncthreads();
    for (int off = 1; off < 128; off <<= 1) {
        int t = (tid >= off) ? s[tid - off] : 0;
        __syncthreads();
        sum += t;
        s[tid] = sum;
        __syncthreads();
    }
    if (tid < nblocks) g_bbase[tid] = sum - v;
}

__global__ void k_finalize() {
    int i = blockIdx.x * blockDim.x + threadIdx.x;
    if (i < NN) {
        g_off[i] = g_partial[i] + g_bbase[i >> 10];
        g_dinv[i] = rsqrtf((float)(g_deg[i] + 1));
    }
    if (i == 0) g_off[NN] = EE;
}

__global__ void k_csr_fill(const int* __restrict__ ei) {
    int i = blockIdx.x * blockDim.x + threadIdx.x;
    if (i >= EE / 4) return;
    int4 s4 = ((const int4*)ei)[i];
    int4 d4 = ((const int4*)(ei + EE))[i];
    uchar4 r = ((const uchar4*)g_rank)[i];
    g_csr16[g_off[d4.x] + r.x] = (unsigned short)(s4.x - (s4.x / NG) * NG);
    g_csr16[g_off[d4.y] + r.y] = (unsigned short)(s4.y - (s4.y / NG) * NG);
    g_csr16[g_off[d4.z] + r.z] = (unsigned short)(s4.z - (s4.z / NG) * NG);
    g_csr16[g_off[d4.w] + r.w] = (unsigned short)(s4.w - (s4.w / NG) * NG);
}

// ---------------- proj1: bufA[n] = fp16( dinv[n] * (emb[x[n]] @ W1) ) ----------------
__global__ void k_proj1(const int* __restrict__ x, const float* __restrict__ emb,
                        const float* __restrict__ W1) {
    __shared__ float Ws[64 * 32];
    int tid = threadIdx.x;
    for (int i = tid; i < 64 * 32; i += blockDim.x) Ws[i] = W1[i];
    __syncthreads();
    int warp = (blockIdx.x * blockDim.x + tid) >> 5;
    int lane = tid & 31;
    if (warp >= NN) return;
    int xi = __ldg(&x[warp]);
    const float* er = emb + (long long)xi * 64;
    float e0 = __ldg(&er[lane]);
    float e1 = __ldg(&er[32 + lane]);
    float acc = 0.f;
#pragma unroll
    for (int k = 0; k < 32; k++)
        acc += __shfl_sync(0xffffffffu, e0, k) * Ws[k * 32 + lane];
#pragma unroll
    for (int k = 0; k < 32; k++)
        acc += __shfl_sync(0xffffffffu, e1, k) * Ws[(32 + k) * 32 + lane];
    g_bufA[warp * 32 + lane] = __float2half_rn(acc * g_dinv[warp]);
}

// ---------------- fp16 gather core ----------------
// lane l: edge-group g = l>>2 (8 edges in flight), chunk c = l&3 (feats 8c..8c+7)
// returns per-lane acc[8] = totals for feats [8c, 8c+8) (duplicated across g)
__device__ __forceinline__ void warp_gather_h(const __half* __restrict__ buf,
                                              int d, int gbase, int g, int c, int lane,
                                              float* acc) {
#pragma unroll
    for (int i = 0; i < 8; i++) acc[i] = 0.f;
    if (g == 0) {  // self-loop term (already * dinv[d])
        uint4 raw = *(const uint4*)(buf + (size_t)d * 32 + c * 8);
        add8(acc, raw);
    }
    int s0 = g_off[d], s1 = g_off[d + 1];
    for (int e = s0; e < s1; e += 32) {
        int my = (e + lane < s1) ? (int)g_csr16[e + lane] : 0;
        int n = s1 - e;   // may exceed 32; idx guard below uses min via idx<n with n>=32 full
#pragma unroll
        for (int t = 0; t < 4; t++) {
            int idx = t * 8 + g;
            int src = __shfl_sync(0xffffffffu, my, idx);
            if (idx < n) {
                uint4 raw = *(const uint4*)(buf + (size_t)(gbase + src) * 32 + c * 8);
                add8(acc, raw);
            }
        }
    }
    // reduce the 8 edge-groups (lane bits 2,3,4)
#pragma unroll
    for (int off = 4; off <= 16; off <<= 1) {
#pragma unroll
        for (int i = 0; i < 8; i++)
            acc[i] += __shfl_xor_sync(0xffffffffu, acc[i], off);
    }
}

// layer 1: gather bufA -> relu -> fused proj2 -> bufB = fp16(dinv*(h1@W2))
__global__ void k_agg1(const float* __restrict__ b1, const float* __restrict__ W2) {
    __shared__ float W2s[32 * 32];
    int tid = threadIdx.x;
    for (int i = tid; i < 32 * 32; i += blockDim.x) W2s[i] = W2[i];
    __syncthreads();
    int warp = (blockIdx.x * blockDim.x + tid) >> 5;
    if (warp >= NN) return;
    int l = tid & 31, g = l >> 2, c = l & 3;
    int d = warp;
    int gbase = (d / NG) * NG;
    float acc[8];
    warp_gather_h(g_bufA, d, gbase, g, c, l, acc);
    float dv = g_dinv[d];
    float h8[8];
#pragma unroll
    for (int i = 0; i < 8; i++)
        h8[i] = fmaxf(acc[i] * dv + b1[c * 8 + i], 0.f);
    // fused proj2: o[l] = dv * sum_k h_k * W2[k][l]
    float o = 0.f;
#pragma unroll
    for (int k = 0; k < 32; k++) {
        float hk = __shfl_sync(0xffffffffu, h8[k & 7], k >> 3);
        o += hk * W2s[k * 32 + l];
    }
    g_bufB[(size_t)d * 32 + l] = __float2half_rn(o * dv);
}

// layer 2: gather bufB -> relu -> store bufA (fp16) + fused score
__global__ void k_agg2(const float* __restrict__ b2, const float* __restrict__ pool_w) {
    int tid = threadIdx.x;
    int warp = (blockIdx.x * blockDim.x + tid) >> 5;
    if (warp >= NN) return;
    int l = tid & 31, g = l >> 2, c = l & 3;
    int d = warp;
    int gbase = (d / NG) * NG;
    float acc[8];
    warp_gather_h(g_bufB, d, gbase, g, c, l, acc);
    float dv = g_dinv[d];
    float h8[8];
    float s = 0.f, n2 = 0.f;
#pragma unroll
    for (int i = 0; i < 8; i++) {
        h8[i] = fmaxf(acc[i] * dv + b2[c * 8 + i], 0.f);
        float pw = pool_w[c * 8 + i];
        s  += h8[i] * pw;
        n2 += pw * pw;
    }
    if (g == 0)
        *(uint4*)(g_bufA + (size_t)d * 32 + c * 8) = pack8(h8);
    // sum the 4 chunks (lane bits 0,1)
#pragma unroll
    for (int off = 1; off <= 2; off <<= 1) {
        s  += __shfl_xor_sync(0xffffffffu, s,  off);
        n2 += __shfl_xor_sync(0xffffffffu, n2, off);
    }
    if (l == 0) g_score[d] = tanhf(s * rsqrtf(n2));
}

// ---------------- per-graph top-K + gather-max + MLP head ----------------
__global__ void k_topk_head(const float* __restrict__ dense_W, const float* __restrict__ dense_b,
                            const float* __restrict__ out_W, const float* __restrict__ out_b,
                            float* __restrict__ out) {
    __shared__ unsigned long long keys[2048];
    __shared__ float red[32 * 33];
    __shared__ float gv[32];
    __shared__ float dvs[64];
    int b = blockIdx.x;
    int tid = threadIdx.x;  // 1024 threads

    for (int i = tid; i < 2048; i += 1024) {
        unsigned long long key = 0ull;
        if (i < NG) {
            unsigned u = __float_as_uint(g_score[b * NG + i]);
            u = (u & 0x80000000u) ? ~u : (u | 0x80000000u);
            key = ((unsigned long long)u << 32) | (unsigned long long)(0xFFFFFFFFu - (unsigned)i);
        }
        keys[i] = key;
    }
    __syncthreads();

    for (int k = 2; k <= 2048; k <<= 1) {
        for (int j = k >> 1; j > 0; j >>= 1) {
            for (int i = tid; i < 2048; i += 1024) {
                int ixj = i ^ j;
                if (ixj > i) {
                    bool up = ((i & k) == 0);
                    unsigned long long a = keys[i], cc = keys[ixj];
                    if ((a > cc) == up) { keys[i] = cc; keys[ixj] = a; }
                }
            }
            __syncthreads();
        }
    }

    int j = tid & 31, c = tid >> 5;
    float m = -INFINITY;
    for (int t = c; t < KTOP; t += 32) {
        unsigned long long key = keys[448 + t];
        unsigned up = (unsigned)(key >> 32);
        float val = (up & 0x80000000u) ? __uint_as_float(up ^ 0x80000000u)
                                       : __uint_as_float(~up);
        int idx = (int)(0xFFFFFFFFu - (unsigned)key);
        float hv = __half2float(g_bufA[(size_t)(b * NG + idx) * 32 + j]);
        m = fmaxf(m, hv * val);
    }
    red[c * 33 + j] = m;
    __syncthreads();
    if (c == 0) {
        for (int cc = 1; cc < 32; cc++) m = fmaxf(m, red[cc * 33 + j]);
        gv[j] = m;
    }
    __syncthreads();
    if (tid < DENSE) {
        float s = dense_b[tid];
#pragma unroll
        for (int k = 0; k < G2; k++) s += gv[k] * dense_W[k * DENSE + tid];
        dvs[tid] = fmaxf(s, 0.f);
    }
    __syncthreads();
    if (tid < NCLS) {
        float s = out_b[tid];
#pragma unroll
        for (int k = 0; k < DENSE; k++) s += dvs[k] * out_W[k * NCLS + tid];
        out[b * NCLS + tid] = s;
    }
}

// ---------------- launch ----------------
extern "C" void kernel_launch(void* const* d_in, const int* in_sizes, int n_in,
                              void* d_out, int out_size) {
    const int*   x       = (const int*)d_in[0];
    const int*   ei      = (const int*)d_in[1];
    const float* emb     = (const float*)d_in[3];
    const float* W1      = (const float*)d_in[4];
    const float* b1      = (const float*)d_in[5];
    const float* W2      = (const float*)d_in[6];
    const float* b2      = (const float*)d_in[7];
    const float* pool_w  = (const float*)d_in[8];
    const float* dense_W = (const float*)d_in[9];
    const float* dense_b = (const float*)d_in[10];
    const float* out_W   = (const float*)d_in[11];
    const float* out_b   = (const float*)d_in[12];
    float* out = (float*)d_out;

    const int TB = 256;
    int gridN4 = (NN / 4 + TB - 1) / TB;
    int gridN  = (NN + TB - 1) / TB;
    int gridE4 = (EE / 4 + TB - 1) / TB;
    int gridNW = (NN * 32 + TB - 1) / TB;
    int nScanB = (NN + 1023) / 1024;  // 125

    k_zero_deg<<<gridN4, TB>>>();
    k_count_deg<<<gridE4, TB>>>(ei);
    k_scan1<<<nScanB, 1024>>>();
    k_scan2<<<1, 128>>>(nScanB);
    k_finalize<<<gridN, TB>>>();
    k_csr_fill<<<gridE4, TB>>>(ei);

    k_proj1<<<gridNW, TB>>>(x, emb, W1);
    k_agg1<<<gridNW, TB>>>(b1, W2);
    k_agg2<<<gridNW, TB>>>(b2, pool_w);

    k_topk_head<<<BB, 1024>>>(dense_W, dense_b, out_W, out_b, out);
}

// round 7
// speedup vs baseline: 1.0346x; 1.0346x over previous
#include <cuda_runtime.h>
#include <cuda_bf16.h>
#include <math.h>

// Problem constants (fixed by the dataset)
#define NN      128000      // nodes = B*NG
#define EE      4096000     // edges = B*EG
#define BB      64          // graphs
#define NG      2000        // nodes per graph
#define EG      64000       // edges per graph (exact, by construction)
#define KTOP    1600
#define EMB     64
#define G1      32
#define G2      32
#define DENSE   64
#define NCLS    10

// ---------------- device scratch ----------------
__device__ int            g_deg[NN];
__device__ int            g_off[NN + 1];
__device__ unsigned char  g_rank[EE];
__device__ unsigned short g_csr16[EE];
__device__ float          g_dinv[NN];
__device__ float          g_bufA[NN * 32];   // proj1 out / final h2
__device__ float          g_bufB[NN * 32];   // dinv*(h1@W2)
__device__ float          g_score[NN];

// ---------------- CSR build ----------------
__global__ void k_zero_deg() {
    int i = blockIdx.x * blockDim.x + threadIdx.x;
    if (i < NN / 4) ((int4*)g_deg)[i] = make_int4(0, 0, 0, 0);
}

// count in-degree; record each edge's rank within its dst (atomic return value)
__global__ void k_count_deg(const int* __restrict__ ei) {
    int i = blockIdx.x * blockDim.x + threadIdx.x;
    if (i >= EE / 4) return;
    int4 d4 = ((const int4*)(ei + EE))[i];
    uchar4 r;
    r.x = (unsigned char)atomicAdd(&g_deg[d4.x], 1);
    r.y = (unsigned char)atomicAdd(&g_deg[d4.y], 1);
    r.z = (unsigned char)atomicAdd(&g_deg[d4.z], 1);
    r.w = (unsigned char)atomicAdd(&g_deg[d4.w], 1);
    ((uchar4*)g_rank)[i] = r;
}

// per-graph exclusive scan: graph b's edges occupy [b*EG, (b+1)*EG).
// 64 blocks x 1024 threads; 2 nodes per thread; Hillis-Steele over thread sums.
__global__ void k_scan_graph() {
    __shared__ int ssum[1024];
    int b = blockIdx.x, tid = threadIdx.x;
    int base = b * NG;
    int i0 = tid * 2, i1 = tid * 2 + 1;
    int d0 = (i0 < NG) ? g_deg[base + i0] : 0;
    int d1 = (i1 < NG) ? g_deg[base + i1] : 0;
    int s = d0 + d1;
    int sum = s;
    ssum[tid] = sum;
    __syncthreads();
    for (int off = 1; off < 1024; off <<= 1) {
        int t = (tid >= off) ? ssum[tid - off] : 0;
        __syncthreads();
        sum += t;
        ssum[tid] = sum;
        __syncthreads();
    }
    int excl = sum - s;                       // exclusive over thread-pairs
    int off0 = b * EG + excl;
    if (i0 < NG) {
        g_off[base + i0] = off0;
        g_dinv[base + i0] = rsqrtf((float)(d0 + 1));
    }
    if (i1 < NG) {
        g_off[base + i1] = off0 + d0;
        g_dinv[base + i1] = rsqrtf((float)(d1 + 1));
    }
    if (b == BB - 1 && tid == 0) g_off[NN] = EE;
}

// atomic-free fill: pos = off[dst] + saved rank; store LOCAL src index as u16
__global__ void k_csr_fill(const int* __restrict__ ei) {
    int i = blockIdx.x * blockDim.x + threadIdx.x;
    if (i >= EE / 4) return;
    int4 s4 = ((const int4*)ei)[i];
    int4 d4 = ((const int4*)(ei + EE))[i];
    uchar4 r = ((const uchar4*)g_rank)[i];
    g_csr16[g_off[d4.x] + r.x] = (unsigned short)(s4.x - (s4.x / NG) * NG);
    g_csr16[g_off[d4.y] + r.y] = (unsigned short)(s4.y - (s4.y / NG) * NG);
    g_csr16[g_off[d4.z] + r.z] = (unsigned short)(s4.z - (s4.z / NG) * NG);
    g_csr16[g_off[d4.w] + r.w] = (unsigned short)(s4.w - (s4.w / NG) * NG);
}

// ---------------- proj1: bufA[n] = dinv[n] * (emb[x[n]] @ W1)  (64 -> 32) ----------------
__global__ void k_proj1(const int* __restrict__ x, const float* __restrict__ emb,
                        const float* __restrict__ W1) {
    __shared__ float Ws[64 * 32];
    int tid = threadIdx.x;
    for (int i = tid; i < 64 * 32; i += blockDim.x) Ws[i] = W1[i];
    __syncthreads();
    int warp = (blockIdx.x * blockDim.x + tid) >> 5;
    int lane = tid & 31;
    if (warp >= NN) return;
    int xi = __ldg(&x[warp]);
    const float* er = emb + (long long)xi * 64;
    float e0 = __ldg(&er[lane]);
    float e1 = __ldg(&er[32 + lane]);
    float acc = 0.f;
#pragma unroll
    for (int k = 0; k < 32; k++)
        acc += __shfl_sync(0xffffffffu, e0, k) * Ws[k * 32 + lane];
#pragma unroll
    for (int k = 0; k < 32; k++)
        acc += __shfl_sync(0xffffffffu, e1, k) * Ws[(32 + k) * 32 + lane];
    g_bufA[warp * 32 + lane] = acc * g_dinv[warp];
}

// ---------------- gather core: warp per dst, smem-staged indices ----------------
// lane l: edge-group g = l>>3 (4 edge slots), chunk c = l&7 (feats 4c..4c+3)
// Indices staged to smem so all 8 row-gathers of a 32-edge chunk issue independently.
__device__ __forceinline__ float4 warp_gather(const float* __restrict__ buf,
                                              unsigned short* sidx,
                                              int d, int gbase, int g, int c, int lane) {
    float4 acc;
    if (g == 0) acc = *(const float4*)&buf[(size_t)d * 32 + c * 4];  // self-loop
    else        acc = make_float4(0.f, 0.f, 0.f, 0.f);
    int s0 = g_off[d], s1 = g_off[d + 1];
    for (int e = s0; e < s1; e += 32) {
        int n = s1 - e;                        // >=32 means full chunk
        if (e + lane < s1) sidx[lane] = g_csr16[e + lane];
        __syncwarp();
#pragma unroll
        for (int t = 0; t < 8; t++) {
            int idx = t * 4 + g;
            if (idx < n) {
                int src = (int)sidx[idx];
                const float4* p = (const float4*)&buf[(size_t)(gbase + src) * 32 + c * 4];
                float4 v = *p;
                acc.x += v.x; acc.y += v.y; acc.z += v.z; acc.w += v.w;
            }
        }
        __syncwarp();
    }
    // reduce the 4 edge-groups (lane bits 3,4)
#pragma unroll
    for (int off = 8; off <= 16; off <<= 1) {
        acc.x += __shfl_xor_sync(0xffffffffu, acc.x, off);
        acc.y += __shfl_xor_sync(0xffffffffu, acc.y, off);
        acc.z += __shfl_xor_sync(0xffffffffu, acc.z, off);
        acc.w += __shfl_xor_sync(0xffffffffu, acc.w, off);
    }
    return acc;  // every lane holds totals for feats [4c, 4c+4)
}

// layer 1: gather bufA -> relu -> fused proj2 -> bufB = dinv*(h1@W2)
__global__ void k_agg1(const float* __restrict__ b1, const float* __restrict__ W2) {
    __shared__ float W2s[32 * 32];
    __shared__ unsigned short stage[8][32];
    int tid = threadIdx.x;
    for (int i = tid; i < 32 * 32; i += blockDim.x) W2s[i] = W2[i];
    __syncthreads();
    int warp = (blockIdx.x * blockDim.x + tid) >> 5;
    if (warp >= NN) return;
    int w = (tid >> 5) & 7;
    int l = tid & 31, g = l >> 3, c = l & 7;
    int d = warp;
    int gbase = (d / NG) * NG;
    float4 acc = warp_gather(g_bufA, stage[w], d, gbase, g, c, l);
    float dv = g_dinv[d];
    float4 bb = *(const float4*)&b1[c * 4];
    float hc[4];
    hc[0] = fmaxf(acc.x * dv + bb.x, 0.f);
    hc[1] = fmaxf(acc.y * dv + bb.y, 0.f);
    hc[2] = fmaxf(acc.z * dv + bb.z, 0.f);
    hc[3] = fmaxf(acc.w * dv + bb.w, 0.f);
    // fused proj2: o[l] = dv * sum_k h_k * W2[k][l]
    float o = 0.f;
#pragma unroll
    for (int k = 0; k < 32; k++) {
        float hk = __shfl_sync(0xffffffffu, hc[k & 3], k >> 2);
        o += hk * W2s[k * 32 + l];
    }
    g_bufB[(size_t)d * 32 + l] = o * dv;
}

// layer 2: gather bufB -> relu -> store bufA + fused score
__global__ void k_agg2(const float* __restrict__ b2, const float* __restrict__ pool_w) {
    __shared__ unsigned short stage[8][32];
    int tid = threadIdx.x;
    int warp = (blockIdx.x * blockDim.x + tid) >> 5;
    if (warp >= NN) return;
    int w = (tid >> 5) & 7;
    int l = tid & 31, g = l >> 3, c = l & 7;
    int d = warp;
    int gbase = (d / NG) * NG;
    float4 acc = warp_gather(g_bufB, stage[w], d, gbase, g, c, l);
    float dv = g_dinv[d];
    float4 bb = *(const float4*)&b2[c * 4];
    float4 h;
    h.x = fmaxf(acc.x * dv + bb.x, 0.f);
    h.y = fmaxf(acc.y * dv + bb.y, 0.f);
    h.z = fmaxf(acc.z * dv + bb.z, 0.f);
    h.w = fmaxf(acc.w * dv + bb.w, 0.f);
    if (g == 0) *(float4*)&g_bufA[(size_t)d * 32 + c * 4] = h;
    // score = tanh(h . pw / ||pw||)
    float4 pw = *(const float4*)&pool_w[c * 4];
    float s  = h.x * pw.x + h.y * pw.y + h.z * pw.z + h.w * pw.w;
    float n2 = pw.x * pw.x + pw.y * pw.y + pw.z * pw.z + pw.w * pw.w;
#pragma unroll
    for (int off = 1; off <= 4; off <<= 1) {
        s  += __shfl_xor_sync(0xffffffffu, s,  off);
        n2 += __shfl_xor_sync(0xffffffffu, n2, off);
    }
    if (l == 0) g_score[d] = tanhf(s * rsqrtf(n2));
}

// ---------------- per-graph top-K + gather-max + MLP head ----------------
__global__ void k_topk_head(const float* __restrict__ dense_W, const float* __restrict__ dense_b,
                            const float* __restrict__ out_W, const float* __restrict__ out_b,
                            float* __restrict__ out) {
    __shared__ unsigned long long keys[2048];
    __shared__ float red[32 * 33];
    __shared__ float gv[32];
    __shared__ float dvs[64];
    int b = blockIdx.x;
    int tid = threadIdx.x;  // 1024 threads

    for (int i = tid; i < 2048; i += 1024) {
        unsigned long long key = 0ull;
        if (i < NG) {
            unsigned u = __float_as_uint(g_score[b * NG + i]);
            u = (u & 0x80000000u) ? ~u : (u | 0x80000000u);
            key = ((unsigned long long)u << 32) | (unsigned long long)(0xFFFFFFFFu - (unsigned)i);
        }
        keys[i] = key;
    }
    __syncthreads();

    for (int k = 2; k <= 2048; k <<= 1) {
        for (int j = k >> 1; j > 0; j >>= 1) {
            for (int i = tid; i < 2048; i += 1024) {
                int ixj = i ^ j;
                if (ixj > i) {
                    bool up = ((i & k) == 0);
                    unsigned long long a = keys[i], cc = keys[ixj];
                    if ((a > cc) == up) { keys[i] = cc; keys[ixj] = a; }
                }
            }
            __syncthreads();
        }
    }

    int j = tid & 31, c = tid >> 5;
    float m = -INFINITY;
    for (int t = c; t < KTOP; t += 32) {
        unsigned long long key = keys[448 + t];
        unsigned up = (unsigned)(key >> 32);
        float val = (up & 0x80000000u) ? __uint_as_float(up ^ 0x80000000u)
                                       : __uint_as_float(~up);
        int idx = (int)(0xFFFFFFFFu - (unsigned)key);
        m = fmaxf(m, g_bufA[(size_t)(b * NG + idx) * 32 + j] * val);
    }
    red[c * 33 + j] = m;
    __syncthreads();
    if (c == 0) {
        for (int cc = 1; cc < 32; cc++) m = fmaxf(m, red[cc * 33 + j]);
        gv[j] = m;
    }
    __syncthreads();
    if (tid < DENSE) {
        float s = dense_b[tid];
#pragma unroll
        for (int k = 0; k < G2; k++) s += gv[k] * dense_W[k * DENSE + tid];
        dvs[tid] = fmaxf(s, 0.f);
    }
    __syncthreads();
    if (tid < NCLS) {
        float s = out_b[tid];
#pragma unroll
        for (int k = 0; k < DENSE; k++) s += dvs[k] * out_W[k * NCLS + tid];
        out[b * NCLS + tid] = s;
    }
}

// ---------------- launch ----------------
extern "C" void kernel_launch(void* const* d_in, const int* in_sizes, int n_in,
                              void* d_out, int out_size) {
    const int*   x       = (const int*)d_in[0];
    const int*   ei      = (const int*)d_in[1];
    const float* emb     = (const float*)d_in[3];
    const float* W1      = (const float*)d_in[4];
    const float* b1      = (const float*)d_in[5];
    const float* W2      = (const float*)d_in[6];
    const float* b2      = (const float*)d_in[7];
    const float* pool_w  = (const float*)d_in[8];
    const float* dense_W = (const float*)d_in[9];
    const float* dense_b = (const float*)d_in[10];
    const float* out_W   = (const float*)d_in[11];
    const float* out_b   = (const float*)d_in[12];
    float* out = (float*)d_out;

    const int TB = 256;
    int gridN4 = (NN / 4 + TB - 1) / TB;
    int gridE4 = (EE / 4 + TB - 1) / TB;
    int gridNW = (NN * 32 + TB - 1) / TB;

    k_zero_deg<<<gridN4, TB>>>();
    k_count_deg<<<gridE4, TB>>>(ei);
    k_scan_graph<<<BB, 1024>>>();
    k_csr_fill<<<gridE4, TB>>>(ei);

    k_proj1<<<gridNW, TB>>>(x, emb, W1);
    k_agg1<<<gridNW, TB>>>(b1, W2);
    k_agg2<<<gridNW, TB>>>(b2, pool_w);

    k_topk_head<<<BB, 1024>>>(dense_W, dense_b, out_W, out_b, out);
}